// round 14
// baseline (speedup 1.0000x reference)
#include <cuda_runtime.h>
#include <cuda_fp16.h>
#include <cstdint>

// ---------------- problem constants ----------------
#define BN 2
#define NN 16384
#define BKS 136           // fp16 B row stride (elements): 272 B, conflict-free ldmatrix
#define GRID 148          // 1 CTA/SM — all co-resident (grid barrier requirement)
#define THREADS 256
#define WARPS_PER_CTA 8
#define N_STRIPS_G (BN * NN * 4 / 16)   // 8192 grad strips (16 rows) -> 6.92/warp, util 98.9%
#define N_STRIPS_P (BN * NN / 16)       // 2048 precompute strips

// ---------------- device scratch ----------------
__device__ __align__(256) uint32_t g_gW0h[BN * NN * 64];   // feat@W0[3:]+b0, packed fp16 pairs
__device__ __align__(256) float g_grad[BN * NN * 4 * 3];
__device__ __align__(256) __half g_Wb[2 * 128 * BKS];
__device__ __align__(256) __half g_Wf2T[128 * BKS];
__device__ __align__(256) __half g_W03T[128 * BKS];
__device__ unsigned g_ctr[4];
__device__ unsigned g_barcnt;
__device__ unsigned g_bargen;

// ================= helpers =================
__device__ __forceinline__ uint32_t smem_u32(const void* p) {
    uint32_t a;
    asm("{ .reg .u64 t; cvta.to.shared.u64 t, %1; cvt.u32.u64 %0, t; }" : "=r"(a) : "l"(p));
    return a;
}
__device__ __forceinline__ void ldsm4(uint32_t r[4], uint32_t addr) {
    asm volatile("ldmatrix.sync.aligned.m8n8.x4.shared.b16 {%0,%1,%2,%3}, [%4];"
                 : "=r"(r[0]), "=r"(r[1]), "=r"(r[2]), "=r"(r[3]) : "r"(addr));
}
__device__ __forceinline__ void ldsm2(uint32_t& r0, uint32_t& r1, uint32_t addr) {
    asm volatile("ldmatrix.sync.aligned.m8n8.x2.shared.b16 {%0,%1}, [%2];"
                 : "=r"(r0), "=r"(r1) : "r"(addr));
}
__device__ __forceinline__ void mma_f16(uint32_t& d0, uint32_t& d1,
                                        uint32_t a0, uint32_t a1, uint32_t a2, uint32_t a3,
                                        uint32_t b0, uint32_t b1) {
    asm volatile(
        "mma.sync.aligned.m16n8k16.row.col.f16.f16.f16.f16 "
        "{%0,%1}, {%2,%3,%4,%5}, {%6,%7}, {%0,%1};"
        : "+r"(d0), "+r"(d1)
        : "r"(a0), "r"(a1), "r"(a2), "r"(a3), "r"(b0), "r"(b1));
}
// k=8 variant for the K=3 (zero-padded) h0 GEMM
__device__ __forceinline__ void mma_f16_k8(uint32_t& d0, uint32_t& d1,
                                           uint32_t a0, uint32_t a1, uint32_t b0) {
    asm volatile(
        "mma.sync.aligned.m16n8k8.row.col.f16.f16.f16.f16 "
        "{%0,%1}, {%2,%3}, {%4}, {%0,%1};"
        : "+r"(d0), "+r"(d1)
        : "r"(a0), "r"(a1), "r"(b0));
}
__device__ __forceinline__ void mma_f32(float d[4], uint32_t a0, uint32_t a1,
                                        uint32_t a2, uint32_t a3,
                                        uint32_t b0, uint32_t b1) {
    asm volatile(
        "mma.sync.aligned.m16n8k16.row.col.f32.f16.f16.f32 "
        "{%0,%1,%2,%3}, {%4,%5,%6,%7}, {%8,%9}, {%0,%1,%2,%3};"
        : "+f"(d[0]), "+f"(d[1]), "+f"(d[2]), "+f"(d[3])
        : "r"(a0), "r"(a1), "r"(a2), "r"(a3), "r"(b0), "r"(b1));
}
__device__ __forceinline__ uint32_t packhf(float a, float b) {
    __half2 t = __floats2half2_rn(a, b);
    return *(uint32_t*)&t;
}
__device__ __forceinline__ uint32_t hadd2u(uint32_t a, uint32_t b) {
    __half2 r = __hadd2(*(__half2*)&a, *(__half2*)&b);
    return *(uint32_t*)&r;
}
__device__ __forceinline__ uint32_t hmax2z(uint32_t a) {
    __half2 z = __floats2half2_rn(0.f, 0.f);
    __half2 r = __hmax2(*(__half2*)&a, z);
    return *(uint32_t*)&r;
}

// sense-reversing software grid barrier (all GRID CTAs resident)
__device__ __forceinline__ void grid_bar() {
    __syncthreads();
    if (threadIdx.x == 0) {
        __threadfence();
        unsigned gen;
        asm volatile("ld.volatile.global.u32 %0, [%1];" : "=r"(gen) : "l"(&g_bargen));
        unsigned a = atomicAdd(&g_barcnt, 1u);
        if (a == GRID - 1u) {
            asm volatile("st.volatile.global.u32 [%0], %1;" :: "l"(&g_barcnt), "r"(0u) : "memory");
            __threadfence();
            atomicAdd(&g_bargen, 1u);
        } else {
            unsigned cur;
            do {
                asm volatile("ld.volatile.global.u32 %0, [%1];" : "=r"(cur) : "l"(&g_bargen));
            } while (cur == gen);
        }
        __threadfence();
    }
    __syncthreads();
}

// full-width 16x128x128 warp GEMM, fp16 accumulators
__device__ __forceinline__ void gemm_f16(const uint32_t hA[16][2], uint32_t bBase,
                                         uint32_t acc[16][2]) {
#pragma unroll
    for (int j = 0; j < 16; ++j) { acc[j][0] = 0u; acc[j][1] = 0u; }
#pragma unroll
    for (int s = 0; s < 8; ++s) {
        uint32_t a0 = hA[2 * s][0], a1 = hA[2 * s][1];
        uint32_t a2 = hA[2 * s + 1][0], a3 = hA[2 * s + 1][1];
#pragma unroll
        for (int jj = 0; jj < 8; ++jj) {
            uint32_t bf[4];
            ldsm4(bf, bBase + (uint32_t)(jj * 16 * (BKS * 2)) + s * 32);
            mma_f16(acc[2 * jj][0],     acc[2 * jj][1],     a0, a1, a2, a3, bf[0], bf[1]);
            mma_f16(acc[2 * jj + 1][0], acc[2 * jj + 1][1], a0, a1, a2, a3, bf[2], bf[3]);
        }
    }
}

// ================= SMEM layout =================
#define BMAT_BYTES (128 * BKS * 2)          // 34816
#define BS_BYTES   (2 * BMAT_BYTES)         // 69632
#define WO_OFF     BS_BYTES                 // 16 x 136 x 2 = 4352
#define W03_OFF    (WO_OFF + 4352)          // 128 x 24 x 2 = 6144
#define BB2_OFF    (W03_OFF + 6144)         // 128 u32
#define BF2P_OFF   (BB2_OFF + 512)          // 64 u32
#define B0P_OFF    (BF2P_OFF + 256)         // 64 u32
#define MISC_OFF   (B0P_OFF + 256)          // Wf1 384f + bf1 128f
#define SMEM_TOTAL (MISC_OFF + 2048)        // 83200, 1 CTA/SM

// ================= the fused persistent kernel =================
__global__ __launch_bounds__(THREADS, 1)
void fused_denoise(const float* __restrict__ pcl,
                   const float* __restrict__ Wf1, const float* __restrict__ bf1,
                   const float* __restrict__ Wf2, const float* __restrict__ bf2,
                   const float* __restrict__ W0,  const float* __restrict__ b0,
                   const float* __restrict__ Wb,  const float* __restrict__ bb,
                   const float* __restrict__ Wo,  const float* __restrict__ bo,
                   float* __restrict__ out)
{
    extern __shared__ __align__(256) char smc[];
    const int t    = threadIdx.x;
    const int lane = t & 31;
    const int w    = t >> 5;
    const int gtid = blockIdx.x * THREADS + t;

    char* B_s = smc;
    __half* Wo_s  = (__half*)(smc + WO_OFF);
    __half* W03_s = (__half*)(smc + W03_OFF);
    uint32_t* shBB2  = (uint32_t*)(smc + BB2_OFF);
    uint32_t* shBF2P = (uint32_t*)(smc + BF2P_OFF);
    uint32_t* shB0P  = (uint32_t*)(smc + B0P_OFF);
    float* shWf1 = (float*)(smc + MISC_OFF);
    float* shbf1 = shWf1 + 384;

    // ---------- phase 0: convert weights; reset counters ----------
    for (int idx = gtid; idx < 4 * 128 * 128; idx += GRID * THREADS) {
        int seg = idx >> 14;
        int rem = idx & 16383;
        int n = rem >> 7, k = rem & 127;
        if (seg < 2) {
            g_Wb[seg * 128 * BKS + n * BKS + k] = __float2half(Wb[seg * 16384 + k * 128 + n]);
        } else if (seg == 2) {
            g_Wf2T[n * BKS + k] = __float2half(Wf2[k * 128 + n]);
        } else {
            g_W03T[n * BKS + k] = __float2half(W0[(3 + k) * 128 + n]);
        }
    }
    if (blockIdx.x == 0 && t < 4) g_ctr[t] = 0;
    grid_bar();

    // ---------- stage SMEM ----------
    for (int i = t; i < 384; i += THREADS) shWf1[i] = Wf1[i];
    if (t < 128) shbf1[t] = bf1[t];
    for (int i = t; i < 16 * 128; i += THREADS) {
        int n = i >> 7, k = i & 127;
        Wo_s[n * 136 + k] = (n < 3) ? __float2half(Wo[k * 3 + n]) : __half(0.f);
    }
    for (int i = t; i < 128 * 16; i += THREADS) {
        int n = i >> 4, k = i & 15;
        W03_s[n * 24 + k] = (k < 3) ? __float2half(W0[k * 128 + n]) : __half(0.f);
    }
    if (t < 128) shBB2[t] = packhf(bb[2 * t], bb[2 * t + 1]);
    if (t < 64)  { shBF2P[t] = packhf(bf2[2 * t], bf2[2 * t + 1]);
                   shB0P[t]  = packhf(b0[2 * t],  b0[2 * t + 1]); }
    {
        const uint4* s1 = (const uint4*)g_Wf2T;
        const uint4* s2 = (const uint4*)g_W03T;
        uint4* d1 = (uint4*)B_s;
        uint4* d2 = (uint4*)(B_s + BMAT_BYTES);
        for (int i = t; i < BMAT_BYTES / 16; i += THREADS) { d1[i] = s1[i]; d2[i] = s2[i]; }
    }
    __syncthreads();

    const int rgrp = lane >> 2;
    const int role = lane & 3;
    const int cpos = role * 2;
    const uint32_t bAddr = smem_u32(B_s)
        + (uint32_t)(((lane & 7) + ((lane >> 4) << 3)) * (BKS * 2))
        + (uint32_t)(((lane >> 3) & 1) << 4);
    const uint32_t addrWo = smem_u32(Wo_s)
        + (uint32_t)(((lane & 7) + ((lane >> 4) << 3)) * 272)
        + (uint32_t)(((lane >> 3) & 1) << 4);
    const uint32_t addr03 = smem_u32(W03_s)
        + (uint32_t)(((lane & 7) + ((lane >> 4) << 3)) * 48)
        + (uint32_t)(((lane >> 3) & 1) << 4);

    // ---------- phase 1: precompute (16-point strips) ----------
    for (int sp = blockIdx.x * WARPS_PER_CTA + w; sp < N_STRIPS_P; sp += GRID * WARPS_PER_CTA) {
        const int b  = sp >> 10;
        const int p0 = (sp & 1023) * 16;
        const float* pclb = pcl + ((size_t)b * NN + p0) * 3;
        float* outb = out + ((size_t)b * NN + p0) * 3;
        for (int i = lane; i < 48; i += 32) outb[i] = pclb[i];

        float xl0 = pclb[rgrp * 3 + 0], xl1 = pclb[rgrp * 3 + 1], xl2 = pclb[rgrp * 3 + 2];
        float xh0 = pclb[(rgrp + 8) * 3 + 0], xh1 = pclb[(rgrp + 8) * 3 + 1], xh2 = pclb[(rgrp + 8) * 3 + 2];

        uint32_t hA[16][2];
#pragma unroll
        for (int j = 0; j < 16; ++j) {
            int c = j * 8 + cpos;
            float w0a = shWf1[c],     w1a = shWf1[128 + c],     w2a = shWf1[256 + c],     ba  = shbf1[c];
            float w0b = shWf1[c + 1], w1b = shWf1[128 + c + 1], w2b = shWf1[256 + c + 1], bbv = shbf1[c + 1];
            float vl0 = fmaf(xl0, w0a, fmaf(xl1, w1a, fmaf(xl2, w2a, ba)));
            float vl1 = fmaf(xl0, w0b, fmaf(xl1, w1b, fmaf(xl2, w2b, bbv)));
            float vh0 = fmaf(xh0, w0a, fmaf(xh1, w1a, fmaf(xh2, w2a, ba)));
            float vh1 = fmaf(xh0, w0b, fmaf(xh1, w1b, fmaf(xh2, w2b, bbv)));
            hA[j][0] = packhf(fmaxf(vl0, 0.f), fmaxf(vl1, 0.f));
            hA[j][1] = packhf(fmaxf(vh0, 0.f), fmaxf(vh1, 0.f));
        }

        uint32_t acc[16][2];
        gemm_f16(hA, bAddr, acc);
#pragma unroll
        for (int j = 0; j < 16; ++j) {
            uint32_t bp = shBF2P[j * 4 + role];
            hA[j][0] = hadd2u(acc[j][0], bp);
            hA[j][1] = hadd2u(acc[j][1], bp);
        }

        gemm_f16(hA, bAddr + (uint32_t)BMAT_BYTES, acc);
        {
            uint32_t* gb = g_gW0h + ((size_t)b * NN + p0) * 64;
#pragma unroll
            for (int j = 0; j < 16; ++j) {
                uint32_t bp = shB0P[j * 4 + role];
                gb[(size_t)rgrp * 64 + j * 4 + role]       = hadd2u(acc[j][0], bp);
                gb[(size_t)(rgrp + 8) * 64 + j * 4 + role] = hadd2u(acc[j][1], bp);
            }
        }
    }
    grid_bar();

    // ---------- reload B_s with Wb0, Wb1; preload Wo fragments ----------
    {
        const uint4* src = (const uint4*)g_Wb;
        uint4* dst = (uint4*)B_s;
        for (int i = t; i < BS_BYTES / 16; i += THREADS) dst[i] = src[i];
    }
    __syncthreads();

    uint32_t woF[8][2];
#pragma unroll
    for (int s8 = 0; s8 < 8; ++s8) ldsm2(woF[s8][0], woF[s8][1], addrWo + (uint32_t)(s8 * 32));

    const float bo0 = bo[0], bo1 = bo[1], bo2 = bo[2];
    float s = 0.2f;

    // ---------- 4 denoise steps ----------
    for (int step = 0; step < 4; ++step) {
        unsigned nxt = 0, strip;
        if (lane == 0) nxt = atomicAdd(&g_ctr[step], 1u);
        strip = __shfl_sync(0xffffffffu, nxt, 0);

        while (strip < N_STRIPS_G) {
            if (lane == 0) nxt = atomicAdd(&g_ctr[step], 1u);

            const int b  = (int)(strip >> 12);
            const int p0 = (int)(strip & 4095) * 4;

            int n_lo = p0 + (rgrp >> 2), q_lo = rgrp & 3;
            int n_hi = p0 + ((rgrp + 8) >> 2), q_hi = (rgrp + 8) & 3;
            int m_lo = n_lo + q_lo - 2; m_lo = m_lo < 0 ? 0 : (m_lo > NN - 1 ? NN - 1 : m_lo);
            int m_hi = n_hi + q_hi - 2; m_hi = m_hi < 0 ? 0 : (m_hi > NN - 1 ? NN - 1 : m_hi);

            const float* pcl_b = out + (size_t)b * NN * 3;
            const float* pn_b  = pcl + (size_t)b * NN * 3;
            float cl0 = pcl_b[m_lo * 3 + 0] - pn_b[n_lo * 3 + 0];
            float cl1 = pcl_b[m_lo * 3 + 1] - pn_b[n_lo * 3 + 1];
            float cl2 = pcl_b[m_lo * 3 + 2] - pn_b[n_lo * 3 + 2];
            float ch0 = pcl_b[m_hi * 3 + 0] - pn_b[n_hi * 3 + 0];
            float ch1 = pcl_b[m_hi * 3 + 1] - pn_b[n_hi * 3 + 1];
            float ch2 = pcl_b[m_hi * 3 + 2] - pn_b[n_hi * 3 + 2];

            const uint32_t* gwl = g_gW0h + ((size_t)b * NN + n_lo) * 64;
            const uint32_t* gwh = g_gW0h + ((size_t)b * NN + n_hi) * 64;

            uint32_t caL, caH;
            caL = role == 0 ? packhf(cl0, cl1) : (role == 1 ? packhf(cl2, 0.f) : 0u);
            caH = role == 0 ? packhf(ch0, ch1) : (role == 1 ? packhf(ch2, 0.f) : 0u);

            // h0 = relu(centered @ W0[:3] + gW0) via k8 MMA (K=3 zero-padded to 8)
            uint32_t hA[16][2];
#pragma unroll
            for (int jj = 0; jj < 8; ++jj) {
                uint32_t bf[4];
                ldsm4(bf, addr03 + (uint32_t)(jj * 768));
                uint32_t d00 = 0, d01 = 0, d10 = 0, d11 = 0;
                mma_f16_k8(d00, d01, caL, caH, bf[0]);
                mma_f16_k8(d10, d11, caL, caH, bf[2]);
                int pi = jj * 8 + role;
                hA[2 * jj][0]     = hmax2z(hadd2u(d00, gwl[pi]));
                hA[2 * jj][1]     = hmax2z(hadd2u(d01, gwh[pi]));
                hA[2 * jj + 1][0] = hmax2z(hadd2u(d10, gwl[pi + 4]));
                hA[2 * jj + 1][1] = hmax2z(hadd2u(d11, gwh[pi + 4]));
            }

            // two residual blocks, fp16 acc, in-place epilogues
#pragma unroll
            for (int blk = 0; blk < 2; ++blk) {
                uint32_t acc[16][2];
                gemm_f16(hA, bAddr + (uint32_t)(blk * BMAT_BYTES), acc);
#pragma unroll
                for (int j = 0; j < 16; ++j) {
                    uint32_t bbp = shBB2[blk * 64 + j * 4 + role];
                    hA[j][0] = hadd2u(hA[j][0], hmax2z(hadd2u(acc[j][0], bbp)));
                    hA[j][1] = hadd2u(hA[j][1], hmax2z(hadd2u(acc[j][1], bbp)));
                }
            }

            // grad = h @ Wo + bo via fp32-acc MMA with preloaded Wo fragments
            {
                float accW[4] = {0.f, 0.f, 0.f, 0.f};
#pragma unroll
                for (int s8 = 0; s8 < 8; ++s8)
                    mma_f32(accW, hA[2 * s8][0], hA[2 * s8][1],
                            hA[2 * s8 + 1][0], hA[2 * s8 + 1][1], woF[s8][0], woF[s8][1]);
                float* gp0 = g_grad + (((size_t)b * NN + p0) * 4 + rgrp) * 3;
                float* gp1 = gp0 + 8 * 3;
                if (role == 0) {
                    gp0[0] = accW[0] + bo0; gp0[1] = accW[1] + bo1;
                    gp1[0] = accW[2] + bo0; gp1[1] = accW[3] + bo1;
                } else if (role == 1) {
                    gp0[2] = accW[0] + bo2;
                    gp1[2] = accW[2] + bo2;
                }
            }

            strip = __shfl_sync(0xffffffffu, nxt, 0);
        }
        grid_bar();   // grads visible

        // ---- gather phase ----
        for (int idx = gtid; idx < BN * NN; idx += GRID * THREADS) {
            int b = idx / NN, m = idx - b * NN;
            const float* G = g_grad + (size_t)b * NN * 12;
            float a0 = 0.f, a1 = 0.f, a2 = 0.f;
#pragma unroll
            for (int k = 0; k < 4; ++k) {
                int n = m + 2 - k;
                if (n >= 0 && n < NN) {
                    const float* g = G + ((size_t)n * 4 + k) * 3;
                    a0 += g[0]; a1 += g[1]; a2 += g[2];
                }
            }
            if (m == 0) {
                a0 += G[0] + G[3] + G[12];
                a1 += G[1] + G[4] + G[13];
                a2 += G[2] + G[5] + G[14];
            }
            if (m == NN - 1) {
                const float* g = G + (((size_t)(NN - 1)) * 4 + 3) * 3;
                a0 += g[0]; a1 += g[1]; a2 += g[2];
            }
            float* p = out + (size_t)idx * 3;
            p[0] += s * a0; p[1] += s * a1; p[2] += s * a2;
        }
        if (step < 3) grid_bar();
        s *= 0.95f;
    }
}

// ================= launch =================
extern "C" void kernel_launch(void* const* d_in, const int* in_sizes, int n_in,
                              void* d_out, int out_size)
{
    const float* pcl = (const float*)d_in[0];
    const float* Wf1 = (const float*)d_in[1];
    const float* bf1 = (const float*)d_in[2];
    const float* Wf2 = (const float*)d_in[3];
    const float* bf2 = (const float*)d_in[4];
    const float* W0  = (const float*)d_in[5];
    const float* b0  = (const float*)d_in[6];
    const float* Wb  = (const float*)d_in[7];
    const float* bb  = (const float*)d_in[8];
    const float* Wo  = (const float*)d_in[9];
    const float* bo  = (const float*)d_in[10];
    float* out = (float*)d_out;

    cudaFuncSetAttribute(fused_denoise, cudaFuncAttributeMaxDynamicSharedMemorySize, SMEM_TOTAL);
    fused_denoise<<<GRID, THREADS, SMEM_TOTAL>>>(pcl, Wf1, bf1, Wf2, bf2, W0, b0,
                                                 Wb, bb, Wo, bo, out);
}

// round 15
// speedup vs baseline: 1.0643x; 1.0643x over previous
#include <cuda_runtime.h>
#include <cuda_fp16.h>
#include <cstdint>

// ---------------- problem constants ----------------
#define BN 2
#define NN 16384
#define BKS 136           // fp16 B row stride (elements): 272 B, conflict-free ldmatrix
#define GRID 296          // 148 SMs x 2 CTAs — all co-resident (grid barrier requirement)
#define THREADS 256
#define WARPS_PER_CTA 8
#define N_STRIPS_G (BN * NN * 4 / 16)   // 8192 grad warp strips
#define N_STRIPS_P (BN * NN / 16)       // 2048 precompute warp strips

// ---------------- device scratch ----------------
// g_gW0h permuted layout: word index within a row = role*16 + j  (role=0..3, j=0..15)
__device__ __align__(256) uint32_t g_gW0h[BN * NN * 64];
__device__ __align__(256) float g_grad[BN * NN * 4 * 3];
__device__ __align__(256) __half g_Wb[2 * 128 * BKS];
__device__ __align__(256) __half g_Wf2T[128 * BKS];
__device__ __align__(256) __half g_W03T[128 * BKS];
__device__ unsigned g_ctr[4];
__device__ unsigned g_barcnt;
__device__ unsigned g_bargen;

// ================= helpers =================
__device__ __forceinline__ uint32_t smem_u32(const void* p) {
    uint32_t a;
    asm("{ .reg .u64 t; cvta.to.shared.u64 t, %1; cvt.u32.u64 %0, t; }" : "=r"(a) : "l"(p));
    return a;
}
__device__ __forceinline__ void ldsm4(uint32_t r[4], uint32_t addr) {
    asm volatile("ldmatrix.sync.aligned.m8n8.x4.shared.b16 {%0,%1,%2,%3}, [%4];"
                 : "=r"(r[0]), "=r"(r[1]), "=r"(r[2]), "=r"(r[3]) : "r"(addr));
}
__device__ __forceinline__ void ldsm2(uint32_t& r0, uint32_t& r1, uint32_t addr) {
    asm volatile("ldmatrix.sync.aligned.m8n8.x2.shared.b16 {%0,%1}, [%2];"
                 : "=r"(r0), "=r"(r1) : "r"(addr));
}
__device__ __forceinline__ void mma_f16(uint32_t& d0, uint32_t& d1,
                                        uint32_t a0, uint32_t a1, uint32_t a2, uint32_t a3,
                                        uint32_t b0, uint32_t b1) {
    asm volatile(
        "mma.sync.aligned.m16n8k16.row.col.f16.f16.f16.f16 "
        "{%0,%1}, {%2,%3,%4,%5}, {%6,%7}, {%0,%1};"
        : "+r"(d0), "+r"(d1)
        : "r"(a0), "r"(a1), "r"(a2), "r"(a3), "r"(b0), "r"(b1));
}
// k=8 variant for the K=3 (zero-padded) h0 GEMM
__device__ __forceinline__ void mma_f16_k8(uint32_t& d0, uint32_t& d1,
                                           uint32_t a0, uint32_t a1, uint32_t b0) {
    asm volatile(
        "mma.sync.aligned.m16n8k8.row.col.f16.f16.f16.f16 "
        "{%0,%1}, {%2,%3}, {%4}, {%0,%1};"
        : "+r"(d0), "+r"(d1)
        : "r"(a0), "r"(a1), "r"(b0));
}
__device__ __forceinline__ void mma_f32(float d[4], uint32_t a0, uint32_t a1,
                                        uint32_t a2, uint32_t a3,
                                        uint32_t b0, uint32_t b1) {
    asm volatile(
        "mma.sync.aligned.m16n8k16.row.col.f32.f16.f16.f32 "
        "{%0,%1,%2,%3}, {%4,%5,%6,%7}, {%8,%9}, {%0,%1,%2,%3};"
        : "+f"(d[0]), "+f"(d[1]), "+f"(d[2]), "+f"(d[3])
        : "r"(a0), "r"(a1), "r"(a2), "r"(a3), "r"(b0), "r"(b1));
}
__device__ __forceinline__ uint32_t packhf(float a, float b) {
    __half2 t = __floats2half2_rn(a, b);
    return *(uint32_t*)&t;
}
__device__ __forceinline__ uint32_t hadd2u(uint32_t a, uint32_t b) {
    __half2 r = __hadd2(*(__half2*)&a, *(__half2*)&b);
    return *(uint32_t*)&r;
}
__device__ __forceinline__ uint32_t hmax2z(uint32_t a) {
    __half2 z = __floats2half2_rn(0.f, 0.f);
    __half2 r = __hmax2(*(__half2*)&a, z);
    return *(uint32_t*)&r;
}

// sense-reversing software grid barrier (all GRID CTAs resident)
__device__ __forceinline__ void grid_bar() {
    __syncthreads();
    if (threadIdx.x == 0) {
        __threadfence();
        unsigned gen;
        asm volatile("ld.volatile.global.u32 %0, [%1];" : "=r"(gen) : "l"(&g_bargen));
        unsigned a = atomicAdd(&g_barcnt, 1u);
        if (a == GRID - 1u) {
            asm volatile("st.volatile.global.u32 [%0], %1;" :: "l"(&g_barcnt), "r"(0u) : "memory");
            __threadfence();
            atomicAdd(&g_bargen, 1u);
        } else {
            unsigned cur;
            do {
                asm volatile("ld.volatile.global.u32 %0, [%1];" : "=r"(cur) : "l"(&g_bargen));
            } while (cur == gen);
        }
        __threadfence();
    }
    __syncthreads();
}

// full-width 16x128x128 warp GEMM, fp16 accumulators
__device__ __forceinline__ void gemm_f16(const uint32_t hA[16][2], uint32_t bBase,
                                         uint32_t acc[16][2]) {
#pragma unroll
    for (int j = 0; j < 16; ++j) { acc[j][0] = 0u; acc[j][1] = 0u; }
#pragma unroll
    for (int s = 0; s < 8; ++s) {
        uint32_t a0 = hA[2 * s][0], a1 = hA[2 * s][1];
        uint32_t a2 = hA[2 * s + 1][0], a3 = hA[2 * s + 1][1];
#pragma unroll
        for (int jj = 0; jj < 8; ++jj) {
            uint32_t bf[4];
            ldsm4(bf, bBase + (uint32_t)(jj * 16 * (BKS * 2)) + s * 32);
            mma_f16(acc[2 * jj][0],     acc[2 * jj][1],     a0, a1, a2, a3, bf[0], bf[1]);
            mma_f16(acc[2 * jj + 1][0], acc[2 * jj + 1][1], a0, a1, a2, a3, bf[2], bf[3]);
        }
    }
}

// ================= SMEM layout =================
#define BMAT_BYTES (128 * BKS * 2)          // 34816
#define BS_BYTES   (2 * BMAT_BYTES)         // 69632
#define WO_OFF     BS_BYTES                 // 16 x 136 x 2 = 4352
#define W03_OFF    (WO_OFF + 4352)          // 128 x 24 x 2 = 6144
#define BB2_OFF    (W03_OFF + 6144)         // 128 u32
#define BF2P_OFF   (BB2_OFF + 512)          // 64 u32
#define B0P_OFF    (BF2P_OFF + 256)         // 64 u32
#define MISC_OFF   (B0P_OFF + 256)          // Wf1 384f + bf1 128f
#define SMEM_TOTAL (MISC_OFF + 2048)        // 83200 -> 2 CTAs/SM

// ================= the fused persistent kernel =================
__global__ __launch_bounds__(THREADS, 2)
void fused_denoise(const float* __restrict__ pcl,
                   const float* __restrict__ Wf1, const float* __restrict__ bf1,
                   const float* __restrict__ Wf2, const float* __restrict__ bf2,
                   const float* __restrict__ W0,  const float* __restrict__ b0,
                   const float* __restrict__ Wb,  const float* __restrict__ bb,
                   const float* __restrict__ Wo,  const float* __restrict__ bo,
                   float* __restrict__ out)
{
    extern __shared__ __align__(256) char smc[];
    const int t    = threadIdx.x;
    const int lane = t & 31;
    const int w    = t >> 5;
    const int gtid = blockIdx.x * THREADS + t;

    char* B_s = smc;
    __half* Wo_s  = (__half*)(smc + WO_OFF);
    __half* W03_s = (__half*)(smc + W03_OFF);
    uint32_t* shBB2  = (uint32_t*)(smc + BB2_OFF);
    uint32_t* shBF2P = (uint32_t*)(smc + BF2P_OFF);
    uint32_t* shB0P  = (uint32_t*)(smc + B0P_OFF);
    float* shWf1 = (float*)(smc + MISC_OFF);
    float* shbf1 = shWf1 + 384;

    // ---------- phase 0: convert weights; reset counters ----------
    for (int idx = gtid; idx < 4 * 128 * 128; idx += GRID * THREADS) {
        int seg = idx >> 14;
        int rem = idx & 16383;
        int n = rem >> 7, k = rem & 127;
        if (seg < 2) {
            g_Wb[seg * 128 * BKS + n * BKS + k] = __float2half(Wb[seg * 16384 + k * 128 + n]);
        } else if (seg == 2) {
            g_Wf2T[n * BKS + k] = __float2half(Wf2[k * 128 + n]);
        } else {
            g_W03T[n * BKS + k] = __float2half(W0[(3 + k) * 128 + n]);
        }
    }
    if (blockIdx.x == 0 && t < 4) g_ctr[t] = 0;
    grid_bar();

    // ---------- stage SMEM ----------
    for (int i = t; i < 384; i += THREADS) shWf1[i] = Wf1[i];
    if (t < 128) shbf1[t] = bf1[t];
    for (int i = t; i < 16 * 128; i += THREADS) {
        int n = i >> 7, k = i & 127;
        Wo_s[n * 136 + k] = (n < 3) ? __float2half(Wo[k * 3 + n]) : __half(0.f);
    }
    for (int i = t; i < 128 * 16; i += THREADS) {
        int n = i >> 4, k = i & 15;
        W03_s[n * 24 + k] = (k < 3) ? __float2half(W0[k * 128 + n]) : __half(0.f);
    }
    if (t < 128) shBB2[t] = packhf(bb[2 * t], bb[2 * t + 1]);
    if (t < 64)  { shBF2P[t] = packhf(bf2[2 * t], bf2[2 * t + 1]);
                   shB0P[t]  = packhf(b0[2 * t],  b0[2 * t + 1]); }
    {
        const uint4* s1 = (const uint4*)g_Wf2T;
        const uint4* s2 = (const uint4*)g_W03T;
        uint4* d1 = (uint4*)B_s;
        uint4* d2 = (uint4*)(B_s + BMAT_BYTES);
        for (int i = t; i < BMAT_BYTES / 16; i += THREADS) { d1[i] = s1[i]; d2[i] = s2[i]; }
    }
    __syncthreads();

    const int rgrp = lane >> 2;
    const int role = lane & 3;
    const int cpos = role * 2;
    const uint32_t bAddr = smem_u32(B_s)
        + (uint32_t)(((lane & 7) + ((lane >> 4) << 3)) * (BKS * 2))
        + (uint32_t)(((lane >> 3) & 1) << 4);
    const uint32_t addrWo = smem_u32(Wo_s)
        + (uint32_t)(((lane & 7) + ((lane >> 4) << 3)) * 272)
        + (uint32_t)(((lane >> 3) & 1) << 4);
    const uint32_t addr03 = smem_u32(W03_s)
        + (uint32_t)(((lane & 7) + ((lane >> 4) << 3)) * 48)
        + (uint32_t)(((lane >> 3) & 1) << 4);

    // ---------- phase 1: precompute (one 16-point strip per warp, static) ----------
    {
        const int sp = blockIdx.x * WARPS_PER_CTA + w;
        if (sp < N_STRIPS_P) {
            const int b  = sp >> 10;
            const int p0 = (sp & 1023) * 16;
            const float* pclb = pcl + ((size_t)b * NN + p0) * 3;
            float* outb = out + ((size_t)b * NN + p0) * 3;
            for (int i = lane; i < 48; i += 32) outb[i] = pclb[i];

            float xl0 = pclb[rgrp * 3 + 0], xl1 = pclb[rgrp * 3 + 1], xl2 = pclb[rgrp * 3 + 2];
            float xh0 = pclb[(rgrp + 8) * 3 + 0], xh1 = pclb[(rgrp + 8) * 3 + 1], xh2 = pclb[(rgrp + 8) * 3 + 2];

            uint32_t hA[16][2];
#pragma unroll
            for (int j = 0; j < 16; ++j) {
                int c = j * 8 + cpos;
                float w0a = shWf1[c],     w1a = shWf1[128 + c],     w2a = shWf1[256 + c],     ba  = shbf1[c];
                float w0b = shWf1[c + 1], w1b = shWf1[128 + c + 1], w2b = shWf1[256 + c + 1], bbv = shbf1[c + 1];
                float vl0 = fmaf(xl0, w0a, fmaf(xl1, w1a, fmaf(xl2, w2a, ba)));
                float vl1 = fmaf(xl0, w0b, fmaf(xl1, w1b, fmaf(xl2, w2b, bbv)));
                float vh0 = fmaf(xh0, w0a, fmaf(xh1, w1a, fmaf(xh2, w2a, ba)));
                float vh1 = fmaf(xh0, w0b, fmaf(xh1, w1b, fmaf(xh2, w2b, bbv)));
                hA[j][0] = packhf(fmaxf(vl0, 0.f), fmaxf(vl1, 0.f));
                hA[j][1] = packhf(fmaxf(vh0, 0.f), fmaxf(vh1, 0.f));
            }

            uint32_t acc[16][2];
            gemm_f16(hA, bAddr, acc);
#pragma unroll
            for (int j = 0; j < 16; ++j) {
                uint32_t bp = shBF2P[j * 4 + role];
                hA[j][0] = hadd2u(acc[j][0], bp);
                hA[j][1] = hadd2u(acc[j][1], bp);
            }

            gemm_f16(hA, bAddr + (uint32_t)BMAT_BYTES, acc);
            {
                // permuted layout: word index = role*16 + j  (pairs j=2jj,2jj+1 contiguous)
                uint32_t* gb = g_gW0h + ((size_t)b * NN + p0) * 64;
                uint2* gbl = (uint2*)(gb + (size_t)rgrp * 64 + role * 16);
                uint2* gbh = (uint2*)(gb + (size_t)(rgrp + 8) * 64 + role * 16);
#pragma unroll
                for (int jj = 0; jj < 8; ++jj) {
                    uint32_t bp0 = shB0P[(2 * jj) * 4 + role];
                    uint32_t bp1 = shB0P[(2 * jj + 1) * 4 + role];
                    gbl[jj] = make_uint2(hadd2u(acc[2 * jj][0], bp0), hadd2u(acc[2 * jj + 1][0], bp1));
                    gbh[jj] = make_uint2(hadd2u(acc[2 * jj][1], bp0), hadd2u(acc[2 * jj + 1][1], bp1));
                }
            }
        }
    }
    grid_bar();

    // ---------- reload B_s with Wb0, Wb1; preload Wo fragments ----------
    {
        const uint4* src = (const uint4*)g_Wb;
        uint4* dst = (uint4*)B_s;
        for (int i = t; i < BS_BYTES / 16; i += THREADS) dst[i] = src[i];
    }
    __syncthreads();

    uint32_t woF[8][2];
#pragma unroll
    for (int s8 = 0; s8 < 8; ++s8) ldsm2(woF[s8][0], woF[s8][1], addrWo + (uint32_t)(s8 * 32));

    const float bo0 = bo[0], bo1 = bo[1], bo2 = bo[2];
    float s = 0.2f;

    // ---------- 4 denoise steps ----------
    for (int step = 0; step < 4; ++step) {
        unsigned nxt = 0, strip;
        if (lane == 0) nxt = atomicAdd(&g_ctr[step], 1u);
        strip = __shfl_sync(0xffffffffu, nxt, 0);

        while (strip < N_STRIPS_G) {
            if (lane == 0) nxt = atomicAdd(&g_ctr[step], 1u);

            const int b  = (int)(strip >> 12);
            const int p0 = (int)(strip & 4095) * 4;

            int n_lo = p0 + (rgrp >> 2), q_lo = rgrp & 3;
            int n_hi = p0 + ((rgrp + 8) >> 2), q_hi = (rgrp + 8) & 3;
            int m_lo = n_lo + q_lo - 2; m_lo = m_lo < 0 ? 0 : (m_lo > NN - 1 ? NN - 1 : m_lo);
            int m_hi = n_hi + q_hi - 2; m_hi = m_hi < 0 ? 0 : (m_hi > NN - 1 ? NN - 1 : m_hi);

            const float* pcl_b = out + (size_t)b * NN * 3;
            const float* pn_b  = pcl + (size_t)b * NN * 3;
            float cl0 = pcl_b[m_lo * 3 + 0] - pn_b[n_lo * 3 + 0];
            float cl1 = pcl_b[m_lo * 3 + 1] - pn_b[n_lo * 3 + 1];
            float cl2 = pcl_b[m_lo * 3 + 2] - pn_b[n_lo * 3 + 2];
            float ch0 = pcl_b[m_hi * 3 + 0] - pn_b[n_hi * 3 + 0];
            float ch1 = pcl_b[m_hi * 3 + 1] - pn_b[n_hi * 3 + 1];
            float ch2 = pcl_b[m_hi * 3 + 2] - pn_b[n_hi * 3 + 2];

            const uint2* gwl2 = (const uint2*)(g_gW0h + ((size_t)b * NN + n_lo) * 64 + role * 16);
            const uint2* gwh2 = (const uint2*)(g_gW0h + ((size_t)b * NN + n_hi) * 64 + role * 16);

            uint32_t caL, caH;
            caL = role == 0 ? packhf(cl0, cl1) : (role == 1 ? packhf(cl2, 0.f) : 0u);
            caH = role == 0 ? packhf(ch0, ch1) : (role == 1 ? packhf(ch2, 0.f) : 0u);

            // h0 = relu(centered @ W0[:3] + gW0) via k8 MMA (K=3 zero-padded to 8)
            uint32_t hA[16][2];
#pragma unroll
            for (int jj = 0; jj < 8; ++jj) {
                uint32_t bf[4];
                ldsm4(bf, addr03 + (uint32_t)(jj * 768));
                uint32_t d00 = 0, d01 = 0, d10 = 0, d11 = 0;
                mma_f16_k8(d00, d01, caL, caH, bf[0]);
                mma_f16_k8(d10, d11, caL, caH, bf[2]);
                uint2 gl = gwl2[jj];
                uint2 gh = gwh2[jj];
                hA[2 * jj][0]     = hmax2z(hadd2u(d00, gl.x));
                hA[2 * jj][1]     = hmax2z(hadd2u(d01, gh.x));
                hA[2 * jj + 1][0] = hmax2z(hadd2u(d10, gl.y));
                hA[2 * jj + 1][1] = hmax2z(hadd2u(d11, gh.y));
            }

            // two residual blocks, fp16 acc, in-place epilogues
#pragma unroll
            for (int blk = 0; blk < 2; ++blk) {
                uint32_t acc[16][2];
                gemm_f16(hA, bAddr + (uint32_t)(blk * BMAT_BYTES), acc);
#pragma unroll
                for (int j = 0; j < 16; ++j) {
                    uint32_t bbp = shBB2[blk * 64 + j * 4 + role];
                    hA[j][0] = hadd2u(hA[j][0], hmax2z(hadd2u(acc[j][0], bbp)));
                    hA[j][1] = hadd2u(hA[j][1], hmax2z(hadd2u(acc[j][1], bbp)));
                }
            }

            // grad = h @ Wo + bo via fp32-acc MMA with preloaded Wo fragments
            {
                float accW[4] = {0.f, 0.f, 0.f, 0.f};
#pragma unroll
                for (int s8 = 0; s8 < 8; ++s8)
                    mma_f32(accW, hA[2 * s8][0], hA[2 * s8][1],
                            hA[2 * s8 + 1][0], hA[2 * s8 + 1][1], woF[s8][0], woF[s8][1]);
                float* gp0 = g_grad + (((size_t)b * NN + p0) * 4 + rgrp) * 3;
                float* gp1 = gp0 + 8 * 3;
                if (role == 0) {
                    gp0[0] = accW[0] + bo0; gp0[1] = accW[1] + bo1;
                    gp1[0] = accW[2] + bo0; gp1[1] = accW[3] + bo1;
                } else if (role == 1) {
                    gp0[2] = accW[0] + bo2;
                    gp1[2] = accW[2] + bo2;
                }
            }

            strip = __shfl_sync(0xffffffffu, nxt, 0);
        }
        grid_bar();   // grads visible

        // ---- gather phase ----
        for (int idx = gtid; idx < BN * NN; idx += GRID * THREADS) {
            int b = idx / NN, m = idx - b * NN;
            const float* G = g_grad + (size_t)b * NN * 12;
            float a0 = 0.f, a1 = 0.f, a2 = 0.f;
#pragma unroll
            for (int k = 0; k < 4; ++k) {
                int n = m + 2 - k;
                if (n >= 0 && n < NN) {
                    const float* g = G + ((size_t)n * 4 + k) * 3;
                    a0 += g[0]; a1 += g[1]; a2 += g[2];
                }
            }
            if (m == 0) {
                a0 += G[0] + G[3] + G[12];
                a1 += G[1] + G[4] + G[13];
                a2 += G[2] + G[5] + G[14];
            }
            if (m == NN - 1) {
                const float* g = G + (((size_t)(NN - 1)) * 4 + 3) * 3;
                a0 += g[0]; a1 += g[1]; a2 += g[2];
            }
            float* p = out + (size_t)idx * 3;
            p[0] += s * a0; p[1] += s * a1; p[2] += s * a2;
        }
        if (step < 3) grid_bar();
        s *= 0.95f;
    }
}

// ================= launch =================
extern "C" void kernel_launch(void* const* d_in, const int* in_sizes, int n_in,
                              void* d_out, int out_size)
{
    const float* pcl = (const float*)d_in[0];
    const float* Wf1 = (const float*)d_in[1];
    const float* bf1 = (const float*)d_in[2];
    const float* Wf2 = (const float*)d_in[3];
    const float* bf2 = (const float*)d_in[4];
    const float* W0  = (const float*)d_in[5];
    const float* b0  = (const float*)d_in[6];
    const float* Wb  = (const float*)d_in[7];
    const float* bb  = (const float*)d_in[8];
    const float* Wo  = (const float*)d_in[9];
    const float* bo  = (const float*)d_in[10];
    float* out = (float*)d_out;

    cudaFuncSetAttribute(fused_denoise, cudaFuncAttributeMaxDynamicSharedMemorySize, SMEM_TOTAL);
    fused_denoise<<<GRID, THREADS, SMEM_TOTAL>>>(pcl, Wf1, bf1, Wf2, bf2, W0, b0,
                                                 Wb, bb, Wo, bo, out);
}

// round 16
// speedup vs baseline: 1.1062x; 1.0394x over previous
#include <cuda_runtime.h>
#include <cuda_fp16.h>
#include <cstdint>

// ---------------- problem constants ----------------
#define BN 2
#define NN 16384
#define BKS 136           // fp16 B row stride (elements): 272 B, conflict-free ldmatrix
#define GRID 296          // 148 SMs x 2 CTAs — all co-resident (grid barrier requirement)
#define THREADS 256
#define WARPS_PER_CTA 8
#define N_STRIPS_G (BN * NN * 4 / 16)   // 8192 grad warp strips
#define N_STRIPS_P (BN * NN / 16)       // 2048 precompute warp strips
#define PCLSZ (BN * NN * 3)
#define GRDSZ (BN * NN * 12)

// ---------------- device scratch ----------------
// g_gW0h permuted layout: word index within a row = role*16 + j
__device__ __align__(256) uint32_t g_gW0h[BN * NN * 64];
__device__ __align__(256) float g_pclbuf[2 * PCLSZ];   // double-buffered point state
__device__ __align__(256) float g_gradb[2 * GRDSZ];    // double-buffered grads
__device__ __align__(256) __half g_Wb[2 * 128 * BKS];
__device__ __align__(256) __half g_Wf2T[128 * BKS];
__device__ __align__(256) __half g_W03T[128 * BKS];
__device__ unsigned g_ctr[4];
__device__ unsigned g_barcnt;
__device__ unsigned g_bargen;

// ================= helpers =================
__device__ __forceinline__ uint32_t smem_u32(const void* p) {
    uint32_t a;
    asm("{ .reg .u64 t; cvta.to.shared.u64 t, %1; cvt.u32.u64 %0, t; }" : "=r"(a) : "l"(p));
    return a;
}
__device__ __forceinline__ void ldsm4(uint32_t r[4], uint32_t addr) {
    asm volatile("ldmatrix.sync.aligned.m8n8.x4.shared.b16 {%0,%1,%2,%3}, [%4];"
                 : "=r"(r[0]), "=r"(r[1]), "=r"(r[2]), "=r"(r[3]) : "r"(addr));
}
__device__ __forceinline__ void ldsm2(uint32_t& r0, uint32_t& r1, uint32_t addr) {
    asm volatile("ldmatrix.sync.aligned.m8n8.x2.shared.b16 {%0,%1}, [%2];"
                 : "=r"(r0), "=r"(r1) : "r"(addr));
}
__device__ __forceinline__ void mma_f16(uint32_t& d0, uint32_t& d1,
                                        uint32_t a0, uint32_t a1, uint32_t a2, uint32_t a3,
                                        uint32_t b0, uint32_t b1) {
    asm volatile(
        "mma.sync.aligned.m16n8k16.row.col.f16.f16.f16.f16 "
        "{%0,%1}, {%2,%3,%4,%5}, {%6,%7}, {%0,%1};"
        : "+r"(d0), "+r"(d1)
        : "r"(a0), "r"(a1), "r"(a2), "r"(a3), "r"(b0), "r"(b1));
}
__device__ __forceinline__ void mma_f16_k8(uint32_t& d0, uint32_t& d1,
                                           uint32_t a0, uint32_t a1, uint32_t b0) {
    asm volatile(
        "mma.sync.aligned.m16n8k8.row.col.f16.f16.f16.f16 "
        "{%0,%1}, {%2,%3}, {%4}, {%0,%1};"
        : "+r"(d0), "+r"(d1)
        : "r"(a0), "r"(a1), "r"(b0));
}
__device__ __forceinline__ void mma_f32(float d[4], uint32_t a0, uint32_t a1,
                                        uint32_t a2, uint32_t a3,
                                        uint32_t b0, uint32_t b1) {
    asm volatile(
        "mma.sync.aligned.m16n8k16.row.col.f32.f16.f16.f32 "
        "{%0,%1,%2,%3}, {%4,%5,%6,%7}, {%8,%9}, {%0,%1,%2,%3};"
        : "+f"(d[0]), "+f"(d[1]), "+f"(d[2]), "+f"(d[3])
        : "r"(a0), "r"(a1), "r"(a2), "r"(a3), "r"(b0), "r"(b1));
}
__device__ __forceinline__ uint32_t packhf(float a, float b) {
    __half2 t = __floats2half2_rn(a, b);
    return *(uint32_t*)&t;
}
__device__ __forceinline__ uint32_t hadd2u(uint32_t a, uint32_t b) {
    __half2 r = __hadd2(*(__half2*)&a, *(__half2*)&b);
    return *(uint32_t*)&r;
}
__device__ __forceinline__ uint32_t hmax2z(uint32_t a) {
    __half2 z = __floats2half2_rn(0.f, 0.f);
    __half2 r = __hmax2(*(__half2*)&a, z);
    return *(uint32_t*)&r;
}

// accumulate scattered grads for point m (G pre-offset to batch): same math as old gather
__device__ __forceinline__ float3 acc_point(const float* __restrict__ G, int m) {
    float a0 = 0.f, a1 = 0.f, a2 = 0.f;
#pragma unroll
    for (int k = 0; k < 4; ++k) {
        int n = m + 2 - k;
        if (n >= 0 && n < NN) {
            const float* g = G + ((size_t)n * 4 + k) * 3;
            a0 += g[0]; a1 += g[1]; a2 += g[2];
        }
    }
    if (m == 0) {
        a0 += G[0] + G[3] + G[12];
        a1 += G[1] + G[4] + G[13];
        a2 += G[2] + G[5] + G[14];
    }
    if (m == NN - 1) {
        const float* g = G + (((size_t)(NN - 1)) * 4 + 3) * 3;
        a0 += g[0]; a1 += g[1]; a2 += g[2];
    }
    return make_float3(a0, a1, a2);
}

// sense-reversing software grid barrier (all GRID CTAs resident)
__device__ __forceinline__ void grid_bar() {
    __syncthreads();
    if (threadIdx.x == 0) {
        __threadfence();
        unsigned gen;
        asm volatile("ld.volatile.global.u32 %0, [%1];" : "=r"(gen) : "l"(&g_bargen));
        unsigned a = atomicAdd(&g_barcnt, 1u);
        if (a == GRID - 1u) {
            asm volatile("st.volatile.global.u32 [%0], %1;" :: "l"(&g_barcnt), "r"(0u) : "memory");
            __threadfence();
            atomicAdd(&g_bargen, 1u);
        } else {
            unsigned cur;
            do {
                asm volatile("ld.volatile.global.u32 %0, [%1];" : "=r"(cur) : "l"(&g_bargen));
            } while (cur == gen);
        }
        __threadfence();
    }
    __syncthreads();
}

// full-width 16x128x128 warp GEMM, fp16 accumulators
__device__ __forceinline__ void gemm_f16(const uint32_t hA[16][2], uint32_t bBase,
                                         uint32_t acc[16][2]) {
#pragma unroll
    for (int j = 0; j < 16; ++j) { acc[j][0] = 0u; acc[j][1] = 0u; }
#pragma unroll
    for (int s = 0; s < 8; ++s) {
        uint32_t a0 = hA[2 * s][0], a1 = hA[2 * s][1];
        uint32_t a2 = hA[2 * s + 1][0], a3 = hA[2 * s + 1][1];
#pragma unroll
        for (int jj = 0; jj < 8; ++jj) {
            uint32_t bf[4];
            ldsm4(bf, bBase + (uint32_t)(jj * 16 * (BKS * 2)) + s * 32);
            mma_f16(acc[2 * jj][0],     acc[2 * jj][1],     a0, a1, a2, a3, bf[0], bf[1]);
            mma_f16(acc[2 * jj + 1][0], acc[2 * jj + 1][1], a0, a1, a2, a3, bf[2], bf[3]);
        }
    }
}

// ================= SMEM layout =================
#define BMAT_BYTES (128 * BKS * 2)          // 34816
#define BS_BYTES   (2 * BMAT_BYTES)         // 69632
#define WO_OFF     BS_BYTES                 // 16 x 136 x 2 = 4352
#define W03_OFF    (WO_OFF + 4352)          // 128 x 24 x 2 = 6144
#define BB2_OFF    (W03_OFF + 6144)         // 128 u32
#define BF2P_OFF   (BB2_OFF + 512)          // 64 u32
#define B0P_OFF    (BF2P_OFF + 256)         // 64 u32
#define MISC_OFF   (B0P_OFF + 256)          // Wf1 384f + bf1 128f
#define SMEM_TOTAL (MISC_OFF + 2048)        // 83200 -> 2 CTAs/SM

// ================= the fused persistent kernel =================
__global__ __launch_bounds__(THREADS, 2)
void fused_denoise(const float* __restrict__ pcl,
                   const float* __restrict__ Wf1, const float* __restrict__ bf1,
                   const float* __restrict__ Wf2, const float* __restrict__ bf2,
                   const float* __restrict__ W0,  const float* __restrict__ b0,
                   const float* __restrict__ Wb,  const float* __restrict__ bb,
                   const float* __restrict__ Wo,  const float* __restrict__ bo,
                   float* __restrict__ out)
{
    extern __shared__ __align__(256) char smc[];
    const int t    = threadIdx.x;
    const int lane = t & 31;
    const int w    = t >> 5;
    const int gtid = blockIdx.x * THREADS + t;

    char* B_s = smc;
    __half* Wo_s  = (__half*)(smc + WO_OFF);
    __half* W03_s = (__half*)(smc + W03_OFF);
    uint32_t* shBB2  = (uint32_t*)(smc + BB2_OFF);
    uint32_t* shBF2P = (uint32_t*)(smc + BF2P_OFF);
    uint32_t* shB0P  = (uint32_t*)(smc + B0P_OFF);
    float* shWf1 = (float*)(smc + MISC_OFF);
    float* shbf1 = shWf1 + 384;

    // ---------- phase 0: convert weights; reset counters ----------
    for (int idx = gtid; idx < 4 * 128 * 128; idx += GRID * THREADS) {
        int seg = idx >> 14;
        int rem = idx & 16383;
        int n = rem >> 7, k = rem & 127;
        if (seg < 2) {
            g_Wb[seg * 128 * BKS + n * BKS + k] = __float2half(Wb[seg * 16384 + k * 128 + n]);
        } else if (seg == 2) {
            g_Wf2T[n * BKS + k] = __float2half(Wf2[k * 128 + n]);
        } else {
            g_W03T[n * BKS + k] = __float2half(W0[(3 + k) * 128 + n]);
        }
    }
    if (blockIdx.x == 0 && t < 4) g_ctr[t] = 0;
    grid_bar();

    // ---------- stage SMEM ----------
    for (int i = t; i < 384; i += THREADS) shWf1[i] = Wf1[i];
    if (t < 128) shbf1[t] = bf1[t];
    for (int i = t; i < 16 * 128; i += THREADS) {
        int n = i >> 7, k = i & 127;
        Wo_s[n * 136 + k] = (n < 3) ? __float2half(Wo[k * 3 + n]) : __half(0.f);
    }
    for (int i = t; i < 128 * 16; i += THREADS) {
        int n = i >> 4, k = i & 15;
        W03_s[n * 24 + k] = (k < 3) ? __float2half(W0[k * 128 + n]) : __half(0.f);
    }
    if (t < 128) shBB2[t] = packhf(bb[2 * t], bb[2 * t + 1]);
    if (t < 64)  { shBF2P[t] = packhf(bf2[2 * t], bf2[2 * t + 1]);
                   shB0P[t]  = packhf(b0[2 * t],  b0[2 * t + 1]); }
    {
        const uint4* s1 = (const uint4*)g_Wf2T;
        const uint4* s2 = (const uint4*)g_W03T;
        uint4* d1 = (uint4*)B_s;
        uint4* d2 = (uint4*)(B_s + BMAT_BYTES);
        for (int i = t; i < BMAT_BYTES / 16; i += THREADS) { d1[i] = s1[i]; d2[i] = s2[i]; }
    }
    __syncthreads();

    const int rgrp = lane >> 2;
    const int role = lane & 3;
    const int cpos = role * 2;
    const uint32_t bAddr = smem_u32(B_s)
        + (uint32_t)(((lane & 7) + ((lane >> 4) << 3)) * (BKS * 2))
        + (uint32_t)(((lane >> 3) & 1) << 4);
    const uint32_t addrWo = smem_u32(Wo_s)
        + (uint32_t)(((lane & 7) + ((lane >> 4) << 3)) * 272)
        + (uint32_t)(((lane >> 3) & 1) << 4);
    const uint32_t addr03 = smem_u32(W03_s)
        + (uint32_t)(((lane & 7) + ((lane >> 4) << 3)) * 48)
        + (uint32_t)(((lane >> 3) & 1) << 4);

    // ---------- phase 1: precompute (one 16-point strip per warp, static) ----------
    // also initializes pcl buffer 0 = pcl_noisy
    {
        const int sp = blockIdx.x * WARPS_PER_CTA + w;
        if (sp < N_STRIPS_P) {
            const int b  = sp >> 10;
            const int p0 = (sp & 1023) * 16;
            const float* pclb = pcl + ((size_t)b * NN + p0) * 3;
            float* pbuf0 = g_pclbuf + ((size_t)b * NN + p0) * 3;
            for (int i = lane; i < 48; i += 32) pbuf0[i] = pclb[i];

            float xl0 = pclb[rgrp * 3 + 0], xl1 = pclb[rgrp * 3 + 1], xl2 = pclb[rgrp * 3 + 2];
            float xh0 = pclb[(rgrp + 8) * 3 + 0], xh1 = pclb[(rgrp + 8) * 3 + 1], xh2 = pclb[(rgrp + 8) * 3 + 2];

            uint32_t hA[16][2];
#pragma unroll
            for (int j = 0; j < 16; ++j) {
                int c = j * 8 + cpos;
                float w0a = shWf1[c],     w1a = shWf1[128 + c],     w2a = shWf1[256 + c],     ba  = shbf1[c];
                float w0b = shWf1[c + 1], w1b = shWf1[128 + c + 1], w2b = shWf1[256 + c + 1], bbv = shbf1[c + 1];
                float vl0 = fmaf(xl0, w0a, fmaf(xl1, w1a, fmaf(xl2, w2a, ba)));
                float vl1 = fmaf(xl0, w0b, fmaf(xl1, w1b, fmaf(xl2, w2b, bbv)));
                float vh0 = fmaf(xh0, w0a, fmaf(xh1, w1a, fmaf(xh2, w2a, ba)));
                float vh1 = fmaf(xh0, w0b, fmaf(xh1, w1b, fmaf(xh2, w2b, bbv)));
                hA[j][0] = packhf(fmaxf(vl0, 0.f), fmaxf(vl1, 0.f));
                hA[j][1] = packhf(fmaxf(vh0, 0.f), fmaxf(vh1, 0.f));
            }

            uint32_t acc[16][2];
            gemm_f16(hA, bAddr, acc);
#pragma unroll
            for (int j = 0; j < 16; ++j) {
                uint32_t bp = shBF2P[j * 4 + role];
                hA[j][0] = hadd2u(acc[j][0], bp);
                hA[j][1] = hadd2u(acc[j][1], bp);
            }

            gemm_f16(hA, bAddr + (uint32_t)BMAT_BYTES, acc);
            {
                uint32_t* gb = g_gW0h + ((size_t)b * NN + p0) * 64;
                uint2* gbl = (uint2*)(gb + (size_t)rgrp * 64 + role * 16);
                uint2* gbh = (uint2*)(gb + (size_t)(rgrp + 8) * 64 + role * 16);
#pragma unroll
                for (int jj = 0; jj < 8; ++jj) {
                    uint32_t bp0 = shB0P[(2 * jj) * 4 + role];
                    uint32_t bp1 = shB0P[(2 * jj + 1) * 4 + role];
                    gbl[jj] = make_uint2(hadd2u(acc[2 * jj][0], bp0), hadd2u(acc[2 * jj + 1][0], bp1));
                    gbh[jj] = make_uint2(hadd2u(acc[2 * jj][1], bp0), hadd2u(acc[2 * jj + 1][1], bp1));
                }
            }
        }
    }
    grid_bar();

    // ---------- reload B_s with Wb0, Wb1; preload Wo fragments ----------
    {
        const uint4* src = (const uint4*)g_Wb;
        uint4* dst = (uint4*)B_s;
        for (int i = t; i < BS_BYTES / 16; i += THREADS) dst[i] = src[i];
    }
    __syncthreads();

    uint32_t woF[8][2];
#pragma unroll
    for (int s8 = 0; s8 < 8; ++s8) ldsm2(woF[s8][0], woF[s8][1], addrWo + (uint32_t)(s8 * 32));

    const float bo0 = bo[0], bo1 = bo[1], bo2 = bo[2];
    float s_cur = 0.2f, sprev = 0.f;

    // ---------- 4 denoise steps (gather fused into next step's prologue) ----------
    for (int step = 0; step < 4; ++step) {
        const int rB = step & 1;            // pcl read buffer (holds pcl_{step-1}; step0: pcl_0)
        const int wB = (step + 1) & 1;      // pcl write buffer (pcl_step materialized here)
        const int gW = step & 1;            // grad write buffer for this step
        const int gR = (step + 1) & 1;      // grad read buffer (grads of step-1)

        unsigned nxt = 0, strip;
        if (lane == 0) nxt = atomicAdd(&g_ctr[step], 1u);
        strip = __shfl_sync(0xffffffffu, nxt, 0);

        while (strip < N_STRIPS_G) {
            if (lane == 0) nxt = atomicAdd(&g_ctr[step], 1u);

            const int b  = (int)(strip >> 12);
            const int p0 = (int)(strip & 4095) * 4;

            int n_lo = p0 + (rgrp >> 2), q_lo = rgrp & 3;
            int n_hi = p0 + ((rgrp + 8) >> 2), q_hi = (rgrp + 8) & 3;
            int m_lo = n_lo + q_lo - 2; m_lo = m_lo < 0 ? 0 : (m_lo > NN - 1 ? NN - 1 : m_lo);
            int m_hi = n_hi + q_hi - 2; m_hi = m_hi < 0 ? 0 : (m_hi > NN - 1 ? NN - 1 : m_hi);

            const float* Rb = g_pclbuf + (size_t)rB * PCLSZ + (size_t)b * NN * 3;
            float*       Wbuf = g_pclbuf + (size_t)wB * PCLSZ + (size_t)b * NN * 3;
            const float* pn_b = pcl + (size_t)b * NN * 3;

            // pcl_cur at m_lo/m_hi, computed on the fly (fused gather)
            float pl0, pl1, pl2, ph0, ph1, ph2;
            if (step == 0) {
                pl0 = Rb[m_lo * 3 + 0]; pl1 = Rb[m_lo * 3 + 1]; pl2 = Rb[m_lo * 3 + 2];
                ph0 = Rb[m_hi * 3 + 0]; ph1 = Rb[m_hi * 3 + 1]; ph2 = Rb[m_hi * 3 + 2];
            } else {
                const float* Gp = g_gradb + (size_t)gR * GRDSZ + (size_t)b * NN * 12;
                float3 al = acc_point(Gp, m_lo);
                float3 ah = acc_point(Gp, m_hi);
                pl0 = fmaf(sprev, al.x, Rb[m_lo * 3 + 0]);
                pl1 = fmaf(sprev, al.y, Rb[m_lo * 3 + 1]);
                pl2 = fmaf(sprev, al.z, Rb[m_lo * 3 + 2]);
                ph0 = fmaf(sprev, ah.x, Rb[m_hi * 3 + 0]);
                ph1 = fmaf(sprev, ah.y, Rb[m_hi * 3 + 1]);
                ph2 = fmaf(sprev, ah.z, Rb[m_hi * 3 + 2]);
            }
            // materialize pcl_step: rows with k==2 (rgrp 2 or 6) have m==n, one writer per point
            if (role == 2 && (rgrp == 2 || rgrp == 6)) {
                Wbuf[m_lo * 3 + 0] = pl0; Wbuf[m_lo * 3 + 1] = pl1; Wbuf[m_lo * 3 + 2] = pl2;
                Wbuf[m_hi * 3 + 0] = ph0; Wbuf[m_hi * 3 + 1] = ph1; Wbuf[m_hi * 3 + 2] = ph2;
            }

            float cl0 = pl0 - pn_b[n_lo * 3 + 0];
            float cl1 = pl1 - pn_b[n_lo * 3 + 1];
            float cl2 = pl2 - pn_b[n_lo * 3 + 2];
            float ch0 = ph0 - pn_b[n_hi * 3 + 0];
            float ch1 = ph1 - pn_b[n_hi * 3 + 1];
            float ch2 = ph2 - pn_b[n_hi * 3 + 2];

            const uint2* gwl2 = (const uint2*)(g_gW0h + ((size_t)b * NN + n_lo) * 64 + role * 16);
            const uint2* gwh2 = (const uint2*)(g_gW0h + ((size_t)b * NN + n_hi) * 64 + role * 16);

            uint32_t caL, caH;
            caL = role == 0 ? packhf(cl0, cl1) : (role == 1 ? packhf(cl2, 0.f) : 0u);
            caH = role == 0 ? packhf(ch0, ch1) : (role == 1 ? packhf(ch2, 0.f) : 0u);

            // h0 = relu(centered @ W0[:3] + gW0) via k8 MMA
            uint32_t hA[16][2];
#pragma unroll
            for (int jj = 0; jj < 8; ++jj) {
                uint32_t bf[4];
                ldsm4(bf, addr03 + (uint32_t)(jj * 768));
                uint32_t d00 = 0, d01 = 0, d10 = 0, d11 = 0;
                mma_f16_k8(d00, d01, caL, caH, bf[0]);
                mma_f16_k8(d10, d11, caL, caH, bf[2]);
                uint2 gl = gwl2[jj];
                uint2 gh = gwh2[jj];
                hA[2 * jj][0]     = hmax2z(hadd2u(d00, gl.x));
                hA[2 * jj][1]     = hmax2z(hadd2u(d01, gh.x));
                hA[2 * jj + 1][0] = hmax2z(hadd2u(d10, gl.y));
                hA[2 * jj + 1][1] = hmax2z(hadd2u(d11, gh.y));
            }

            // two residual blocks
#pragma unroll
            for (int blk = 0; blk < 2; ++blk) {
                uint32_t acc[16][2];
                gemm_f16(hA, bAddr + (uint32_t)(blk * BMAT_BYTES), acc);
#pragma unroll
                for (int j = 0; j < 16; ++j) {
                    uint32_t bbp = shBB2[blk * 64 + j * 4 + role];
                    hA[j][0] = hadd2u(hA[j][0], hmax2z(hadd2u(acc[j][0], bbp)));
                    hA[j][1] = hadd2u(hA[j][1], hmax2z(hadd2u(acc[j][1], bbp)));
                }
            }

            // grad = h @ Wo + bo
            {
                float accW[4] = {0.f, 0.f, 0.f, 0.f};
#pragma unroll
                for (int s8 = 0; s8 < 8; ++s8)
                    mma_f32(accW, hA[2 * s8][0], hA[2 * s8][1],
                            hA[2 * s8 + 1][0], hA[2 * s8 + 1][1], woF[s8][0], woF[s8][1]);
                float* Gw = g_gradb + (size_t)gW * GRDSZ;
                float* gp0 = Gw + (((size_t)b * NN + p0) * 4 + rgrp) * 3;
                float* gp1 = gp0 + 8 * 3;
                if (role == 0) {
                    gp0[0] = accW[0] + bo0; gp0[1] = accW[1] + bo1;
                    gp1[0] = accW[2] + bo0; gp1[1] = accW[3] + bo1;
                } else if (role == 1) {
                    gp0[2] = accW[0] + bo2;
                    gp1[2] = accW[2] + bo2;
                }
            }

            strip = __shfl_sync(0xffffffffu, nxt, 0);
        }
        grid_bar();   // grads + materialized pcl visible before next step

        sprev = s_cur;
        s_cur *= 0.95f;
    }

    // ---------- final pass: out = pcl_3 + s_3 * acc(grads_3) ----------
    {
        const float* Rb = g_pclbuf + (size_t)0 * PCLSZ;     // pcl_3 is in buffer (3+1)&1 = 0
        for (int idx = gtid; idx < BN * NN; idx += GRID * THREADS) {
            int b = idx / NN, m = idx - b * NN;
            const float* Gp = g_gradb + (size_t)1 * GRDSZ + (size_t)b * NN * 12;  // grads_3 in buf 3&1=1
            float3 a = acc_point(Gp, m);
            float* p = out + (size_t)idx * 3;
            const float* r = Rb + (size_t)idx * 3;
            p[0] = fmaf(sprev, a.x, r[0]);
            p[1] = fmaf(sprev, a.y, r[1]);
            p[2] = fmaf(sprev, a.z, r[2]);
        }
    }
}

// ================= launch =================
extern "C" void kernel_launch(void* const* d_in, const int* in_sizes, int n_in,
                              void* d_out, int out_size)
{
    const float* pcl = (const float*)d_in[0];
    const float* Wf1 = (const float*)d_in[1];
    const float* bf1 = (const float*)d_in[2];
    const float* Wf2 = (const float*)d_in[3];
    const float* bf2 = (const float*)d_in[4];
    const float* W0  = (const float*)d_in[5];
    const float* b0  = (const float*)d_in[6];
    const float* Wb  = (const float*)d_in[7];
    const float* bb  = (const float*)d_in[8];
    const float* Wo  = (const float*)d_in[9];
    const float* bo  = (const float*)d_in[10];
    float* out = (float*)d_out;

    cudaFuncSetAttribute(fused_denoise, cudaFuncAttributeMaxDynamicSharedMemorySize, SMEM_TOTAL);
    fused_denoise<<<GRID, THREADS, SMEM_TOTAL>>>(pcl, Wf1, bf1, Wf2, bf2, W0, b0,
                                                 Wb, bb, Wo, bo, out);
}

// round 17
// speedup vs baseline: 1.1165x; 1.0094x over previous
#include <cuda_runtime.h>
#include <cuda_fp16.h>
#include <cstdint>

// ---------------- problem constants ----------------
#define BN 2
#define NN 16384
#define BKS 136           // fp16 B row stride (elements): 272 B, conflict-free ldmatrix
#define GRID 296          // 148 SMs x 2 CTAs — all co-resident (grid barrier requirement)
#define THREADS 256
#define WARPS_PER_CTA 8
#define N_STRIPS_G (BN * NN * 4 / 16)   // 8192 grad warp strips
#define N_STRIPS_P (BN * NN / 16)       // 2048 precompute warp strips
#define PCLSZ (BN * NN * 3)
#define GRDSZ (BN * NN * 12)

// ---------------- device scratch ----------------
// g_gW0h permuted layout: word index within a row = role*16 + j
__device__ __align__(256) uint32_t g_gW0h[BN * NN * 64];
__device__ __align__(256) float g_pclbuf[2 * PCLSZ];   // double-buffered point state
__device__ __align__(256) float g_gradb[2 * GRDSZ];    // double-buffered grads
__device__ __align__(256) __half g_Wb[2 * 128 * BKS];
__device__ __align__(256) __half g_Wf2T[128 * BKS];
__device__ __align__(256) __half g_W03T[128 * BKS];
__device__ unsigned g_ctr[4];
__device__ unsigned g_barcnt;
__device__ unsigned g_bargen;

// ================= helpers =================
__device__ __forceinline__ uint32_t smem_u32(const void* p) {
    uint32_t a;
    asm("{ .reg .u64 t; cvta.to.shared.u64 t, %1; cvt.u32.u64 %0, t; }" : "=r"(a) : "l"(p));
    return a;
}
__device__ __forceinline__ void ldsm4(uint32_t r[4], uint32_t addr) {
    asm volatile("ldmatrix.sync.aligned.m8n8.x4.shared.b16 {%0,%1,%2,%3}, [%4];"
                 : "=r"(r[0]), "=r"(r[1]), "=r"(r[2]), "=r"(r[3]) : "r"(addr));
}
__device__ __forceinline__ void ldsm2(uint32_t& r0, uint32_t& r1, uint32_t addr) {
    asm volatile("ldmatrix.sync.aligned.m8n8.x2.shared.b16 {%0,%1}, [%2];"
                 : "=r"(r0), "=r"(r1) : "r"(addr));
}
__device__ __forceinline__ void mma_f16(uint32_t& d0, uint32_t& d1,
                                        uint32_t a0, uint32_t a1, uint32_t a2, uint32_t a3,
                                        uint32_t b0, uint32_t b1) {
    asm volatile(
        "mma.sync.aligned.m16n8k16.row.col.f16.f16.f16.f16 "
        "{%0,%1}, {%2,%3,%4,%5}, {%6,%7}, {%0,%1};"
        : "+r"(d0), "+r"(d1)
        : "r"(a0), "r"(a1), "r"(a2), "r"(a3), "r"(b0), "r"(b1));
}
__device__ __forceinline__ void mma_f16_k8(uint32_t& d0, uint32_t& d1,
                                           uint32_t a0, uint32_t a1, uint32_t b0) {
    asm volatile(
        "mma.sync.aligned.m16n8k8.row.col.f16.f16.f16.f16 "
        "{%0,%1}, {%2,%3}, {%4}, {%0,%1};"
        : "+r"(d0), "+r"(d1)
        : "r"(a0), "r"(a1), "r"(b0));
}
__device__ __forceinline__ void mma_f32(float d[4], uint32_t a0, uint32_t a1,
                                        uint32_t a2, uint32_t a3,
                                        uint32_t b0, uint32_t b1) {
    asm volatile(
        "mma.sync.aligned.m16n8k16.row.col.f32.f16.f16.f32 "
        "{%0,%1,%2,%3}, {%4,%5,%6,%7}, {%8,%9}, {%0,%1,%2,%3};"
        : "+f"(d[0]), "+f"(d[1]), "+f"(d[2]), "+f"(d[3])
        : "r"(a0), "r"(a1), "r"(a2), "r"(a3), "r"(b0), "r"(b1));
}
__device__ __forceinline__ uint32_t packhf(float a, float b) {
    __half2 t = __floats2half2_rn(a, b);
    return *(uint32_t*)&t;
}
__device__ __forceinline__ uint32_t hadd2u(uint32_t a, uint32_t b) {
    __half2 r = __hadd2(*(__half2*)&a, *(__half2*)&b);
    return *(uint32_t*)&r;
}
__device__ __forceinline__ uint32_t hmax2z(uint32_t a) {
    __half2 z = __floats2half2_rn(0.f, 0.f);
    __half2 r = __hmax2(*(__half2*)&a, z);
    return *(uint32_t*)&r;
}

// accumulate scattered grads for point m (G pre-offset to batch)
__device__ __forceinline__ float3 acc_point(const float* __restrict__ G, int m) {
    float a0 = 0.f, a1 = 0.f, a2 = 0.f;
#pragma unroll
    for (int k = 0; k < 4; ++k) {
        int n = m + 2 - k;
        if (n >= 0 && n < NN) {
            const float* g = G + ((size_t)n * 4 + k) * 3;
            a0 += g[0]; a1 += g[1]; a2 += g[2];
        }
    }
    if (m == 0) {
        a0 += G[0] + G[3] + G[12];
        a1 += G[1] + G[4] + G[13];
        a2 += G[2] + G[5] + G[14];
    }
    if (m == NN - 1) {
        const float* g = G + (((size_t)(NN - 1)) * 4 + 3) * 3;
        a0 += g[0]; a1 += g[1]; a2 += g[2];
    }
    return make_float3(a0, a1, a2);
}

// sense-reversing software grid barrier (all GRID CTAs resident)
__device__ __forceinline__ void grid_bar() {
    __syncthreads();
    if (threadIdx.x == 0) {
        __threadfence();
        unsigned gen;
        asm volatile("ld.volatile.global.u32 %0, [%1];" : "=r"(gen) : "l"(&g_bargen));
        unsigned a = atomicAdd(&g_barcnt, 1u);
        if (a == GRID - 1u) {
            asm volatile("st.volatile.global.u32 [%0], %1;" :: "l"(&g_barcnt), "r"(0u) : "memory");
            __threadfence();
            atomicAdd(&g_bargen, 1u);
        } else {
            unsigned cur;
            do {
                asm volatile("ld.volatile.global.u32 %0, [%1];" : "=r"(cur) : "l"(&g_bargen));
            } while (cur == gen);
        }
        __threadfence();
    }
    __syncthreads();
}

// full-width 16x128x128 warp GEMM, fp16 accumulators
__device__ __forceinline__ void gemm_f16(const uint32_t hA[16][2], uint32_t bBase,
                                         uint32_t acc[16][2]) {
#pragma unroll
    for (int j = 0; j < 16; ++j) { acc[j][0] = 0u; acc[j][1] = 0u; }
#pragma unroll
    for (int s = 0; s < 8; ++s) {
        uint32_t a0 = hA[2 * s][0], a1 = hA[2 * s][1];
        uint32_t a2 = hA[2 * s + 1][0], a3 = hA[2 * s + 1][1];
#pragma unroll
        for (int jj = 0; jj < 8; ++jj) {
            uint32_t bf[4];
            ldsm4(bf, bBase + (uint32_t)(jj * 16 * (BKS * 2)) + s * 32);
            mma_f16(acc[2 * jj][0],     acc[2 * jj][1],     a0, a1, a2, a3, bf[0], bf[1]);
            mma_f16(acc[2 * jj + 1][0], acc[2 * jj + 1][1], a0, a1, a2, a3, bf[2], bf[3]);
        }
    }
}

// ================= SMEM layout =================
#define BMAT_BYTES (128 * BKS * 2)          // 34816
#define BS_BYTES   (2 * BMAT_BYTES)         // 69632
#define WO_OFF     BS_BYTES                 // 16 x 136 x 2 = 4352
#define W03_OFF    (WO_OFF + 4352)          // 128 x 24 x 2 = 6144
#define BB2_OFF    (W03_OFF + 6144)         // 128 u32
#define BF2P_OFF   (BB2_OFF + 512)          // 64 u32
#define B0P_OFF    (BF2P_OFF + 256)         // 64 u32
#define MISC_OFF   (B0P_OFF + 256)          // Wf1 384f + bf1 128f
#define SMEM_TOTAL (MISC_OFF + 2048)        // 83200 -> 2 CTAs/SM

// ================= the fused persistent kernel =================
__global__ __launch_bounds__(THREADS, 2)
void fused_denoise(const float* __restrict__ pcl,
                   const float* __restrict__ Wf1, const float* __restrict__ bf1,
                   const float* __restrict__ Wf2, const float* __restrict__ bf2,
                   const float* __restrict__ W0,  const float* __restrict__ b0,
                   const float* __restrict__ Wb,  const float* __restrict__ bb,
                   const float* __restrict__ Wo,  const float* __restrict__ bo,
                   float* __restrict__ out)
{
    extern __shared__ __align__(256) char smc[];
    const int t    = threadIdx.x;
    const int lane = t & 31;
    const int w    = t >> 5;
    const int gtid = blockIdx.x * THREADS + t;

    char* B_s = smc;
    __half* Wo_s  = (__half*)(smc + WO_OFF);
    __half* W03_s = (__half*)(smc + W03_OFF);
    uint32_t* shBB2  = (uint32_t*)(smc + BB2_OFF);
    uint32_t* shBF2P = (uint32_t*)(smc + BF2P_OFF);
    uint32_t* shB0P  = (uint32_t*)(smc + B0P_OFF);
    float* shWf1 = (float*)(smc + MISC_OFF);
    float* shbf1 = shWf1 + 384;

    // ---------- phase 0: convert weights; reset counters ----------
    for (int idx = gtid; idx < 4 * 128 * 128; idx += GRID * THREADS) {
        int seg = idx >> 14;
        int rem = idx & 16383;
        int n = rem >> 7, k = rem & 127;
        if (seg < 2) {
            g_Wb[seg * 128 * BKS + n * BKS + k] = __float2half(Wb[seg * 16384 + k * 128 + n]);
        } else if (seg == 2) {
            g_Wf2T[n * BKS + k] = __float2half(Wf2[k * 128 + n]);
        } else {
            g_W03T[n * BKS + k] = __float2half(W0[(3 + k) * 128 + n]);
        }
    }
    if (blockIdx.x == 0 && t < 4) g_ctr[t] = 0;
    grid_bar();

    // ---------- stage SMEM ----------
    for (int i = t; i < 384; i += THREADS) shWf1[i] = Wf1[i];
    if (t < 128) shbf1[t] = bf1[t];
    for (int i = t; i < 16 * 128; i += THREADS) {
        int n = i >> 7, k = i & 127;
        Wo_s[n * 136 + k] = (n < 3) ? __float2half(Wo[k * 3 + n]) : __half(0.f);
    }
    for (int i = t; i < 128 * 16; i += THREADS) {
        int n = i >> 4, k = i & 15;
        W03_s[n * 24 + k] = (k < 3) ? __float2half(W0[k * 128 + n]) : __half(0.f);
    }
    if (t < 128) shBB2[t] = packhf(bb[2 * t], bb[2 * t + 1]);
    if (t < 64)  { shBF2P[t] = packhf(bf2[2 * t], bf2[2 * t + 1]);
                   shB0P[t]  = packhf(b0[2 * t],  b0[2 * t + 1]); }
    {
        const uint4* s1 = (const uint4*)g_Wf2T;
        const uint4* s2 = (const uint4*)g_W03T;
        uint4* d1 = (uint4*)B_s;
        uint4* d2 = (uint4*)(B_s + BMAT_BYTES);
        for (int i = t; i < BMAT_BYTES / 16; i += THREADS) { d1[i] = s1[i]; d2[i] = s2[i]; }
    }
    __syncthreads();

    const int rgrp = lane >> 2;
    const int role = lane & 3;
    const int cpos = role * 2;
    const int qbase = lane & ~3;           // first lane of this quad
    const uint32_t bAddr = smem_u32(B_s)
        + (uint32_t)(((lane & 7) + ((lane >> 4) << 3)) * (BKS * 2))
        + (uint32_t)(((lane >> 3) & 1) << 4);
    const uint32_t addrWo = smem_u32(Wo_s)
        + (uint32_t)(((lane & 7) + ((lane >> 4) << 3)) * 272)
        + (uint32_t)(((lane >> 3) & 1) << 4);
    const uint32_t addr03 = smem_u32(W03_s)
        + (uint32_t)(((lane & 7) + ((lane >> 4) << 3)) * 48)
        + (uint32_t)(((lane >> 3) & 1) << 4);

    // ---------- phase 1: precompute (one 16-point strip per warp, static) ----------
    // also initializes pcl buffer 0 = pcl_noisy
    {
        const int sp = blockIdx.x * WARPS_PER_CTA + w;
        if (sp < N_STRIPS_P) {
            const int b  = sp >> 10;
            const int p0 = (sp & 1023) * 16;
            const float* pclb = pcl + ((size_t)b * NN + p0) * 3;
            float* pbuf0 = g_pclbuf + ((size_t)b * NN + p0) * 3;
            for (int i = lane; i < 48; i += 32) pbuf0[i] = pclb[i];

            float xl0 = pclb[rgrp * 3 + 0], xl1 = pclb[rgrp * 3 + 1], xl2 = pclb[rgrp * 3 + 2];
            float xh0 = pclb[(rgrp + 8) * 3 + 0], xh1 = pclb[(rgrp + 8) * 3 + 1], xh2 = pclb[(rgrp + 8) * 3 + 2];

            uint32_t hA[16][2];
#pragma unroll
            for (int j = 0; j < 16; ++j) {
                int c = j * 8 + cpos;
                float w0a = shWf1[c],     w1a = shWf1[128 + c],     w2a = shWf1[256 + c],     ba  = shbf1[c];
                float w0b = shWf1[c + 1], w1b = shWf1[128 + c + 1], w2b = shWf1[256 + c + 1], bbv = shbf1[c + 1];
                float vl0 = fmaf(xl0, w0a, fmaf(xl1, w1a, fmaf(xl2, w2a, ba)));
                float vl1 = fmaf(xl0, w0b, fmaf(xl1, w1b, fmaf(xl2, w2b, bbv)));
                float vh0 = fmaf(xh0, w0a, fmaf(xh1, w1a, fmaf(xh2, w2a, ba)));
                float vh1 = fmaf(xh0, w0b, fmaf(xh1, w1b, fmaf(xh2, w2b, bbv)));
                hA[j][0] = packhf(fmaxf(vl0, 0.f), fmaxf(vl1, 0.f));
                hA[j][1] = packhf(fmaxf(vh0, 0.f), fmaxf(vh1, 0.f));
            }

            uint32_t acc[16][2];
            gemm_f16(hA, bAddr, acc);
#pragma unroll
            for (int j = 0; j < 16; ++j) {
                uint32_t bp = shBF2P[j * 4 + role];
                hA[j][0] = hadd2u(acc[j][0], bp);
                hA[j][1] = hadd2u(acc[j][1], bp);
            }

            gemm_f16(hA, bAddr + (uint32_t)BMAT_BYTES, acc);
            {
                uint32_t* gb = g_gW0h + ((size_t)b * NN + p0) * 64;
                uint2* gbl = (uint2*)(gb + (size_t)rgrp * 64 + role * 16);
                uint2* gbh = (uint2*)(gb + (size_t)(rgrp + 8) * 64 + role * 16);
#pragma unroll
                for (int jj = 0; jj < 8; ++jj) {
                    uint32_t bp0 = shB0P[(2 * jj) * 4 + role];
                    uint32_t bp1 = shB0P[(2 * jj + 1) * 4 + role];
                    gbl[jj] = make_uint2(hadd2u(acc[2 * jj][0], bp0), hadd2u(acc[2 * jj + 1][0], bp1));
                    gbh[jj] = make_uint2(hadd2u(acc[2 * jj][1], bp0), hadd2u(acc[2 * jj + 1][1], bp1));
                }
            }
        }
    }
    grid_bar();

    // ---------- reload B_s with Wb0, Wb1; preload Wo fragments ----------
    {
        const uint4* src = (const uint4*)g_Wb;
        uint4* dst = (uint4*)B_s;
        for (int i = t; i < BS_BYTES / 16; i += THREADS) dst[i] = src[i];
    }
    __syncthreads();

    uint32_t woF[8][2];
#pragma unroll
    for (int s8 = 0; s8 < 8; ++s8) ldsm2(woF[s8][0], woF[s8][1], addrWo + (uint32_t)(s8 * 32));

    const float bo0 = bo[0], bo1 = bo[1], bo2 = bo[2];
    float s_cur = 0.2f, sprev = 0.f;

    // ---------- 4 denoise steps (gather fused, quad-deduplicated) ----------
    for (int step = 0; step < 4; ++step) {
        const int rB = step & 1;
        const int wB = (step + 1) & 1;
        const int gW = step & 1;
        const int gR = (step + 1) & 1;

        unsigned nxt = 0, strip;
        if (lane == 0) nxt = atomicAdd(&g_ctr[step], 1u);
        strip = __shfl_sync(0xffffffffu, nxt, 0);

        while (strip < N_STRIPS_G) {
            if (lane == 0) nxt = atomicAdd(&g_ctr[step], 1u);

            const int b  = (int)(strip >> 12);
            const int p0 = (int)(strip & 4095) * 4;

            int n_lo = p0 + (rgrp >> 2), q_lo = rgrp & 3;
            int n_hi = p0 + ((rgrp + 8) >> 2), q_hi = (rgrp + 8) & 3;
            int m_lo = n_lo + q_lo - 2; m_lo = m_lo < 0 ? 0 : (m_lo > NN - 1 ? NN - 1 : m_lo);
            int m_hi = n_hi + q_hi - 2; m_hi = m_hi < 0 ? 0 : (m_hi > NN - 1 ? NN - 1 : m_hi);

            const float* Rb = g_pclbuf + (size_t)rB * PCLSZ + (size_t)b * NN * 3;
            float*       Wbuf = g_pclbuf + (size_t)wB * PCLSZ + (size_t)b * NN * 3;
            const float* pn_b = pcl + (size_t)b * NN * 3;

            // quad-deduplicated fused gather: role 0 owns m_lo, role 1 owns m_hi
            float pv0, pv1, pv2;
            {
                int mm = (role == 1) ? m_hi : m_lo;
                if (step == 0) {
                    pv0 = Rb[mm * 3 + 0]; pv1 = Rb[mm * 3 + 1]; pv2 = Rb[mm * 3 + 2];
                } else {
                    const float* Gp = g_gradb + (size_t)gR * GRDSZ + (size_t)b * NN * 12;
                    float3 a = (role <= 1) ? acc_point(Gp, mm) : make_float3(0.f, 0.f, 0.f);
                    pv0 = fmaf(sprev, a.x, Rb[mm * 3 + 0]);
                    pv1 = fmaf(sprev, a.y, Rb[mm * 3 + 1]);
                    pv2 = fmaf(sprev, a.z, Rb[mm * 3 + 2]);
                }
            }
            float pl0 = __shfl_sync(0xffffffffu, pv0, qbase);
            float pl1 = __shfl_sync(0xffffffffu, pv1, qbase);
            float pl2 = __shfl_sync(0xffffffffu, pv2, qbase);
            float ph0 = __shfl_sync(0xffffffffu, pv0, qbase + 1);
            float ph1 = __shfl_sync(0xffffffffu, pv1, qbase + 1);
            float ph2 = __shfl_sync(0xffffffffu, pv2, qbase + 1);

            // materialize pcl_step: rows with k==2 (rgrp 2 or 6) have m==n, one writer per point
            if (role == 2 && (rgrp == 2 || rgrp == 6)) {
                Wbuf[m_lo * 3 + 0] = pl0; Wbuf[m_lo * 3 + 1] = pl1; Wbuf[m_lo * 3 + 2] = pl2;
                Wbuf[m_hi * 3 + 0] = ph0; Wbuf[m_hi * 3 + 1] = ph1; Wbuf[m_hi * 3 + 2] = ph2;
            }

            float cl0 = pl0 - pn_b[n_lo * 3 + 0];
            float cl1 = pl1 - pn_b[n_lo * 3 + 1];
            float cl2 = pl2 - pn_b[n_lo * 3 + 2];
            float ch0 = ph0 - pn_b[n_hi * 3 + 0];
            float ch1 = ph1 - pn_b[n_hi * 3 + 1];
            float ch2 = ph2 - pn_b[n_hi * 3 + 2];

            const uint2* gwl2 = (const uint2*)(g_gW0h + ((size_t)b * NN + n_lo) * 64 + role * 16);
            const uint2* gwh2 = (const uint2*)(g_gW0h + ((size_t)b * NN + n_hi) * 64 + role * 16);

            uint32_t caL, caH;
            caL = role == 0 ? packhf(cl0, cl1) : (role == 1 ? packhf(cl2, 0.f) : 0u);
            caH = role == 0 ? packhf(ch0, ch1) : (role == 1 ? packhf(ch2, 0.f) : 0u);

            // h0 = relu(centered @ W0[:3] + gW0) via k8 MMA
            uint32_t hA[16][2];
#pragma unroll
            for (int jj = 0; jj < 8; ++jj) {
                uint32_t bf[4];
                ldsm4(bf, addr03 + (uint32_t)(jj * 768));
                uint32_t d00 = 0, d01 = 0, d10 = 0, d11 = 0;
                mma_f16_k8(d00, d01, caL, caH, bf[0]);
                mma_f16_k8(d10, d11, caL, caH, bf[2]);
                uint2 gl = gwl2[jj];
                uint2 gh = gwh2[jj];
                hA[2 * jj][0]     = hmax2z(hadd2u(d00, gl.x));
                hA[2 * jj][1]     = hmax2z(hadd2u(d01, gh.x));
                hA[2 * jj + 1][0] = hmax2z(hadd2u(d10, gl.y));
                hA[2 * jj + 1][1] = hmax2z(hadd2u(d11, gh.y));
            }

            // two residual blocks
#pragma unroll
            for (int blk = 0; blk < 2; ++blk) {
                uint32_t acc[16][2];
                gemm_f16(hA, bAddr + (uint32_t)(blk * BMAT_BYTES), acc);
#pragma unroll
                for (int j = 0; j < 16; ++j) {
                    uint32_t bbp = shBB2[blk * 64 + j * 4 + role];
                    hA[j][0] = hadd2u(hA[j][0], hmax2z(hadd2u(acc[j][0], bbp)));
                    hA[j][1] = hadd2u(hA[j][1], hmax2z(hadd2u(acc[j][1], bbp)));
                }
            }

            // grad = h @ Wo + bo
            {
                float accW[4] = {0.f, 0.f, 0.f, 0.f};
#pragma unroll
                for (int s8 = 0; s8 < 8; ++s8)
                    mma_f32(accW, hA[2 * s8][0], hA[2 * s8][1],
                            hA[2 * s8 + 1][0], hA[2 * s8 + 1][1], woF[s8][0], woF[s8][1]);
                float* Gw = g_gradb + (size_t)gW * GRDSZ;
                float* gp0 = Gw + (((size_t)b * NN + p0) * 4 + rgrp) * 3;
                float* gp1 = gp0 + 8 * 3;
                if (role == 0) {
                    gp0[0] = accW[0] + bo0; gp0[1] = accW[1] + bo1;
                    gp1[0] = accW[2] + bo0; gp1[1] = accW[3] + bo1;
                } else if (role == 1) {
                    gp0[2] = accW[0] + bo2;
                    gp1[2] = accW[2] + bo2;
                }
            }

            strip = __shfl_sync(0xffffffffu, nxt, 0);
        }
        grid_bar();   // grads + materialized pcl visible before next step

        sprev = s_cur;
        s_cur *= 0.95f;
    }

    // ---------- final pass: out = pcl_3 + s_3 * acc(grads_3) ----------
    {
        const float* Rb = g_pclbuf;                              // pcl_3 in buffer (3+1)&1 = 0
        for (int idx = gtid; idx < BN * NN; idx += GRID * THREADS) {
            int b = idx / NN, m = idx - b * NN;
            const float* Gp = g_gradb + (size_t)1 * GRDSZ + (size_t)b * NN * 12;  // grads_3 in buf 1
            float3 a = acc_point(Gp, m);
            float* p = out + (size_t)idx * 3;
            const float* r = Rb + (size_t)idx * 3;
            p[0] = fmaf(sprev, a.x, r[0]);
            p[1] = fmaf(sprev, a.y, r[1]);
            p[2] = fmaf(sprev, a.z, r[2]);
        }
    }
}

// ================= launch =================
extern "C" void kernel_launch(void* const* d_in, const int* in_sizes, int n_in,
                              void* d_out, int out_size)
{
    const float* pcl = (const float*)d_in[0];
    const float* Wf1 = (const float*)d_in[1];
    const float* bf1 = (const float*)d_in[2];
    const float* Wf2 = (const float*)d_in[3];
    const float* bf2 = (const float*)d_in[4];
    const float* W0  = (const float*)d_in[5];
    const float* b0  = (const float*)d_in[6];
    const float* Wb  = (const float*)d_in[7];
    const float* bb  = (const float*)d_in[8];
    const float* Wo  = (const float*)d_in[9];
    const float* bo  = (const float*)d_in[10];
    float* out = (float*)d_out;

    cudaFuncSetAttribute(fused_denoise, cudaFuncAttributeMaxDynamicSharedMemorySize, SMEM_TOTAL);
    fused_denoise<<<GRID, THREADS, SMEM_TOTAL>>>(pcl, Wf1, bf1, Wf2, bf2, W0, b0,
                                                 Wb, bb, Wo, bo, out);
}